// round 14
// baseline (speedup 1.0000x reference)
#include <cuda_runtime.h>
#include <cuda_bf16.h>
#include <cstdint>
#include <math.h>

// SpatialGRU 32x32, B=64,U=64,C=64.
// R14: 32 groups x 4 CTAs. CTA0/1: r-cols (Z in regs -> G from frags -> P_s).
// CTA2/3: z-cols publish. All: 16-col epilogue. bf16 hi/lo 3-term mma.sync.

#define TPB 256
#define LDA 200
#define LDW 200
#define LDU 104
#define LDZ 65

__device__ float    g_x[1024 * 4096];
__device__ float    g_XZ[1024 * 28672];   // x@W+bias col-major [c448][r64]; z-cols -> Z
__device__ float    g_xWij[1024 * 4096];
__device__ uint32_t g_Spk[1024 * 4096];   // packed h: lo16 = hi-bf16, hi16 = lo-bf16
__device__ float    g_P[1024 * 2 * 4096]; // 2 partials per cell, col-major [n][r]
__device__ int      g_pz[1024];           // bits: P0,P1,Z2,Z3 -> full 0xF
__device__ int      g_hdone[1024];        // bits per CTA -> full 0xF

// smem offsets (bytes)
#define O_AH 0
#define O_AL 25600
#define O_WH 51200
#define O_WL 102400
#define O_UH 153600
#define O_UL 166912
#define O_GH 180224
#define O_GL 193536
#define O_ZS 206848
#define SMEMSZ 223488

static __device__ __forceinline__ void mma16816(float* c, const uint32_t* a,
                                                const uint32_t* b) {
    asm volatile(
        "mma.sync.aligned.m16n8k16.row.col.f32.bf16.bf16.f32 "
        "{%0,%1,%2,%3}, {%4,%5,%6,%7}, {%8,%9}, {%0,%1,%2,%3};"
        : "+f"(c[0]), "+f"(c[1]), "+f"(c[2]), "+f"(c[3])
        : "r"(a[0]), "r"(a[1]), "r"(a[2]), "r"(a[3]), "r"(b[0]), "r"(b[1]));
}
static __device__ __forceinline__ int ld_acq(const int* p) {
    int v;
    asm volatile("ld.acquire.gpu.global.b32 %0, [%1];" : "=r"(v) : "l"(p) : "memory");
    return v;
}
static __device__ __forceinline__ void red_rel_or(int* p, int v) {
    asm volatile("red.release.gpu.global.or.b32 [%0], %1;" :: "l"(p), "r"(v) : "memory");
}

// ---------------------------------------------------------------------------
__global__ void k_init() {
    int idx = blockIdx.x * blockDim.x + threadIdx.x;
    if (idx < 1024) { g_pz[idx] = 0; g_hdone[idx] = 0; }
}

__global__ void k_transpose(const float* __restrict__ in) {
    __shared__ float tile[32][33];
    int b = blockIdx.z, t0 = blockIdx.x * 32, c0 = blockIdx.y * 32;
    int tx = threadIdx.x, ty = threadIdx.y;
    tile[ty][tx] = in[b * 65536 + (c0 + ty) * 1024 + t0 + tx];
    __syncthreads();
    g_x[(t0 + ty) * 4096 + b * 64 + c0 + tx] = tile[tx][ty];
}

// XZ[t] = x@W[192:256]+bias[:448] (col-major [c][r]); xWij[t] = x@W_ij + b_ij
__global__ void k_pre(const float* __restrict__ W, const float* __restrict__ Wij,
                      const float* __restrict__ bias) {
    __shared__ float sXT[64 * 65];
    __shared__ float sB[64 * 64];
    int t = blockIdx.x, ct = blockIdx.y, tid = threadIdx.x;
    for (int idx = tid; idx < 4096; idx += TPB) {
        int rr = idx >> 6, k = idx & 63;
        sXT[k * 65 + rr] = g_x[t * 4096 + idx];
        sB[idx] = (ct < 7) ? W[(192 + rr) * 448 + ct * 64 + k] : Wij[rr * 64 + k];
    }
    __syncthreads();
    int r = tid & 63, cb = (tid >> 6) << 4;
    const float* bs = (ct < 7) ? (bias + ct * 64 + cb) : (bias + 448 + cb);
    float acc[16];
#pragma unroll
    for (int s = 0; s < 16; ++s) acc[s] = bs[s];
#pragma unroll 4
    for (int k = 0; k < 64; ++k) {
        float a = sXT[k * 65 + r];
        const float4* bp = (const float4*)&sB[k * 64 + cb];
        float4 b0 = bp[0], b1 = bp[1], b2 = bp[2], b3 = bp[3];
        acc[0] += a*b0.x; acc[1] += a*b0.y; acc[2] += a*b0.z; acc[3] += a*b0.w;
        acc[4] += a*b1.x; acc[5] += a*b1.y; acc[6] += a*b1.z; acc[7] += a*b1.w;
        acc[8] += a*b2.x; acc[9] += a*b2.y; acc[10] += a*b2.z; acc[11] += a*b2.w;
        acc[12] += a*b3.x; acc[13] += a*b3.y; acc[14] += a*b3.z; acc[15] += a*b3.w;
    }
    __syncthreads();
    if (ct < 7) {
#pragma unroll
        for (int s = 0; s < 16; ++s) sB[(cb + s) * 64 + r] = acc[s];
        __syncthreads();
        for (int idx = tid; idx < 4096; idx += TPB) {
            int c = idx >> 6, r2 = idx & 63;
            g_XZ[t * 28672 + (ct * 64 + c) * 64 + r2] = sB[c * 64 + r2];
        }
    } else {
        float* o = &g_xWij[t * 4096 + r * 64 + cb];
#pragma unroll
        for (int s = 0; s < 16; ++s) o[s] = acc[s];
    }
}

// ---------------------------------------------------------------------------
__global__ void __launch_bounds__(TPB, 1)
k_scan(const float* __restrict__ W, const float* __restrict__ Urec,
       float* __restrict__ out) {
    extern __shared__ char sm[];
    __nv_bfloat16* Ah = (__nv_bfloat16*)(sm + O_AH);
    __nv_bfloat16* Al = (__nv_bfloat16*)(sm + O_AL);
    __nv_bfloat16* Wh = (__nv_bfloat16*)(sm + O_WH);
    __nv_bfloat16* Wl = (__nv_bfloat16*)(sm + O_WL);
    __nv_bfloat16* Uh = (__nv_bfloat16*)(sm + O_UH);
    __nv_bfloat16* Ul = (__nv_bfloat16*)(sm + O_UL);
    __nv_bfloat16* Gh = (__nv_bfloat16*)(sm + O_GH);
    __nv_bfloat16* Gl = (__nv_bfloat16*)(sm + O_GL);
    float*         Zs = (float*)(sm + O_ZS);

    int tid = threadIdx.x, w = tid >> 5, lane = tid & 31;
    int g = lane >> 2, q = lane & 3;
    int gp = blockIdx.x >> 2, s = blockIdx.x & 3;
    int colbase = (s == 0) ? 0 : (s == 1 ? 96 : (s == 2 ? 192 : 320));
    int ncols = (s < 2) ? 96 : 128;

    // resident W slice [n_local][k], k=0..191
    for (int idx = tid; idx < ncols * 192; idx += TPB) {
        int n = idx % ncols, k = idx / ncols;
        float v = W[k * 448 + colbase + n];
        __nv_bfloat16 hi = __float2bfloat16(v);
        Wh[n * LDW + k] = hi;
        Wl[n * LDW + k] = __float2bfloat16(v - __bfloat162float(hi));
    }
    // resident U rows s*96..s*96+95 (LTD order), [n][k_local]
    if (s < 2)
        for (int idx = tid; idx < 64 * 96; idx += TPB) {
            int n = idx & 63, k = idx >> 6;
            float v = Urec[(s * 96 + k) * 64 + n];
            __nv_bfloat16 hi = __float2bfloat16(v);
            Uh[n * LDU + k] = hi;
            Ul[n * LDU + k] = __float2bfloat16(v - __bfloat162float(hi));
        }
    __syncthreads();

    int rb = (w & 3) * 16, cg = w >> 2;

    for (int d = 0; d < 63; ++d) {
        int i0 = d > 31 ? d - 31 : 0;
        int nc = (d < 32) ? d + 1 : 63 - d;
        int c = gp;
        if (c >= nc) continue;
        int i = i0 + c, j = d - i, t = i * 32 + j;
        const uint32_t* hpT = (i > 0) ? &g_Spk[(t - 32) * 4096] : (const uint32_t*)0;
        const uint32_t* hpL = (j > 0) ? &g_Spk[(t - 1) * 4096] : (const uint32_t*)0;
        const uint32_t* hpD = (i > 0 && j > 0) ? &g_Spk[(t - 33) * 4096] : (const uint32_t*)0;
        float* zb = &g_XZ[t * 28672];

        if (tid == 0 && hpT)  while (ld_acq(&g_hdone[t - 32]) != 15) {}
        if (tid == 32 && hpL) while (ld_acq(&g_hdone[t - 1])  != 15) {}
        if (tid == 64 && hpD) while (ld_acq(&g_hdone[t - 33]) != 15) {}
        __syncthreads();

        // ---- A build: [top|left|diag] packed ----
        const uint4* bp3[3] = {(const uint4*)hpT, (const uint4*)hpL, (const uint4*)hpD};
#pragma unroll
        for (int it = 0; it < 12; ++it) {
            int idx = tid + it * TPB;
            int blk = idx >> 10, row = (idx >> 4) & 63, c4 = idx & 15;
            const uint4* p = bp3[blk];
            uint4 v = p ? __ldcg(&p[row * 16 + c4]) : make_uint4(0, 0, 0, 0);
            int cc = blk * 64 + c4 * 4;
            uint32_t* ah = (uint32_t*)&Ah[row * LDA + cc];
            uint32_t* al = (uint32_t*)&Al[row * LDA + cc];
            ah[0] = (v.x & 0xFFFFu) | (v.y << 16);
            ah[1] = (v.z & 0xFFFFu) | (v.w << 16);
            al[0] = (v.x >> 16) | (v.y & 0xFFFF0000u);
            al[1] = (v.z >> 16) | (v.w & 0xFFFF0000u);
        }
        __syncthreads();

        if (s < 2) {
            // ===== r-CTA: Z (96 cols) -> G from frags -> P =====
            float C[6][4];
#pragma unroll
            for (int a = 0; a < 6; ++a)
#pragma unroll
                for (int b = 0; b < 4; ++b) C[a][b] = 0.f;
#pragma unroll 1
            for (int kc = 0; kc < 12; ++kc) {
                int kb = kc * 16;
                uint32_t ah[4], al[4];
                ah[0] = *(const uint32_t*)&Ah[(rb + g) * LDA + kb + q * 2];
                ah[1] = *(const uint32_t*)&Ah[(rb + g + 8) * LDA + kb + q * 2];
                ah[2] = *(const uint32_t*)&Ah[(rb + g) * LDA + kb + 8 + q * 2];
                ah[3] = *(const uint32_t*)&Ah[(rb + g + 8) * LDA + kb + 8 + q * 2];
                al[0] = *(const uint32_t*)&Al[(rb + g) * LDA + kb + q * 2];
                al[1] = *(const uint32_t*)&Al[(rb + g + 8) * LDA + kb + q * 2];
                al[2] = *(const uint32_t*)&Al[(rb + g) * LDA + kb + 8 + q * 2];
                al[3] = *(const uint32_t*)&Al[(rb + g + 8) * LDA + kb + 8 + q * 2];
#pragma unroll
                for (int nb = 0; nb < 6; ++nb) {
                    int n = cg * 48 + nb * 8 + g;
                    uint32_t bh[2], bl[2];
                    bh[0] = *(const uint32_t*)&Wh[n * LDW + kb + q * 2];
                    bh[1] = *(const uint32_t*)&Wh[n * LDW + kb + 8 + q * 2];
                    bl[0] = *(const uint32_t*)&Wl[n * LDW + kb + q * 2];
                    bl[1] = *(const uint32_t*)&Wl[n * LDW + kb + 8 + q * 2];
                    mma16816(C[nb], ah, bh);
                    mma16816(C[nb], al, bh);
                    mma16816(C[nb], ah, bl);
                }
            }
            // G directly from frags: G[row][k_local] = sigmoid(Z+XZ) * A[row][amap]
#pragma unroll
            for (int nb = 0; nb < 6; ++nb)
#pragma unroll
                for (int e = 0; e < 4; ++e) {
                    int row = rb + g + ((e & 2) ? 8 : 0);
                    int cl = cg * 48 + nb * 8 + q * 2 + (e & 1);
                    int rc = colbase + cl;
                    float z = C[nb][e] + __ldcg(&zb[rc * 64 + row]);
                    float sg = 1.f / (1.f + __expf(-z));
                    int ac = rc < 64 ? 64 + rc : (rc < 128 ? rc - 64 : rc);
                    float a = __bfloat162float(Ah[row * LDA + ac]) +
                              __bfloat162float(Al[row * LDA + ac]);
                    float v = sg * a;
                    __nv_bfloat16 hi = __float2bfloat16(v);
                    Gh[row * LDU + cl] = hi;
                    Gl[row * LDU + cl] = __float2bfloat16(v - __bfloat162float(hi));
                }
            __syncthreads();

            // P = G @ U (64x64, K=96)
            float P[4][4];
#pragma unroll
            for (int a = 0; a < 4; ++a)
#pragma unroll
                for (int b = 0; b < 4; ++b) P[a][b] = 0.f;
#pragma unroll 1
            for (int kc = 0; kc < 6; ++kc) {
                int kb = kc * 16;
                uint32_t ah[4], al[4];
                ah[0] = *(const uint32_t*)&Gh[(rb + g) * LDU + kb + q * 2];
                ah[1] = *(const uint32_t*)&Gh[(rb + g + 8) * LDU + kb + q * 2];
                ah[2] = *(const uint32_t*)&Gh[(rb + g) * LDU + kb + 8 + q * 2];
                ah[3] = *(const uint32_t*)&Gh[(rb + g + 8) * LDU + kb + 8 + q * 2];
                al[0] = *(const uint32_t*)&Gl[(rb + g) * LDU + kb + q * 2];
                al[1] = *(const uint32_t*)&Gl[(rb + g + 8) * LDU + kb + q * 2];
                al[2] = *(const uint32_t*)&Gl[(rb + g) * LDU + kb + 8 + q * 2];
                al[3] = *(const uint32_t*)&Gl[(rb + g + 8) * LDU + kb + 8 + q * 2];
#pragma unroll
                for (int nb = 0; nb < 4; ++nb) {
                    int n = cg * 32 + nb * 8 + g;
                    uint32_t bh[2], bl[2];
                    bh[0] = *(const uint32_t*)&Uh[n * LDU + kb + q * 2];
                    bh[1] = *(const uint32_t*)&Uh[n * LDU + kb + 8 + q * 2];
                    bl[0] = *(const uint32_t*)&Ul[n * LDU + kb + q * 2];
                    bl[1] = *(const uint32_t*)&Ul[n * LDU + kb + 8 + q * 2];
                    mma16816(P[nb], ah, bh);
                    mma16816(P[nb], al, bh);
                    mma16816(P[nb], ah, bl);
                }
            }
#pragma unroll
            for (int nb = 0; nb < 4; ++nb) {
                int c0 = cg * 32 + nb * 8 + q * 2;
                Zs[c0 * LDZ + rb + g] = P[nb][0];
                Zs[(c0 + 1) * LDZ + rb + g] = P[nb][1];
                Zs[c0 * LDZ + rb + g + 8] = P[nb][2];
                Zs[(c0 + 1) * LDZ + rb + g + 8] = P[nb][3];
            }
            __syncthreads();
#pragma unroll
            for (int it = 0; it < 16; ++it) {
                int idx = tid + it * TPB;
                int n2 = idx >> 6, r2 = idx & 63;
                __stcg(&g_P[(t * 2 + s) * 4096 + n2 * 64 + r2], Zs[n2 * LDZ + r2]);
            }
            __syncthreads();
            if (tid == 0) red_rel_or(&g_pz[t], 1 << s);
        } else {
            // ===== z-CTA: Z (128 cols) -> publish =====
            float C[8][4];
#pragma unroll
            for (int a = 0; a < 8; ++a)
#pragma unroll
                for (int b = 0; b < 4; ++b) C[a][b] = 0.f;
#pragma unroll 1
            for (int kc = 0; kc < 12; ++kc) {
                int kb = kc * 16;
                uint32_t ah[4], al[4];
                ah[0] = *(const uint32_t*)&Ah[(rb + g) * LDA + kb + q * 2];
                ah[1] = *(const uint32_t*)&Ah[(rb + g + 8) * LDA + kb + q * 2];
                ah[2] = *(const uint32_t*)&Ah[(rb + g) * LDA + kb + 8 + q * 2];
                ah[3] = *(const uint32_t*)&Ah[(rb + g + 8) * LDA + kb + 8 + q * 2];
                al[0] = *(const uint32_t*)&Al[(rb + g) * LDA + kb + q * 2];
                al[1] = *(const uint32_t*)&Al[(rb + g + 8) * LDA + kb + q * 2];
                al[2] = *(const uint32_t*)&Al[(rb + g) * LDA + kb + 8 + q * 2];
                al[3] = *(const uint32_t*)&Al[(rb + g + 8) * LDA + kb + 8 + q * 2];
#pragma unroll
                for (int nb = 0; nb < 8; ++nb) {
                    int n = cg * 64 + nb * 8 + g;
                    uint32_t bh[2], bl[2];
                    bh[0] = *(const uint32_t*)&Wh[n * LDW + kb + q * 2];
                    bh[1] = *(const uint32_t*)&Wh[n * LDW + kb + 8 + q * 2];
                    bl[0] = *(const uint32_t*)&Wl[n * LDW + kb + q * 2];
                    bl[1] = *(const uint32_t*)&Wl[n * LDW + kb + 8 + q * 2];
                    mma16816(C[nb], ah, bh);
                    mma16816(C[nb], al, bh);
                    mma16816(C[nb], ah, bl);
                }
            }
            // publish in two 64-col waves via Zs
#pragma unroll
            for (int wv = 0; wv < 2; ++wv) {
                if (cg == wv)
#pragma unroll
                    for (int nb = 0; nb < 8; ++nb) {
                        int c0 = nb * 8 + q * 2;
                        Zs[c0 * LDZ + rb + g] = C[nb][0];
                        Zs[(c0 + 1) * LDZ + rb + g] = C[nb][1];
                        Zs[c0 * LDZ + rb + g + 8] = C[nb][2];
                        Zs[(c0 + 1) * LDZ + rb + g + 8] = C[nb][3];
                    }
                __syncthreads();
#pragma unroll
                for (int it = 0; it < 16; ++it) {
                    int idx = tid + it * TPB;
                    int cc = idx >> 6, r2 = idx & 63;
                    float* p = &zb[(colbase + wv * 64 + cc) * 64 + r2];
                    __stcg(p, Zs[cc * LDZ + r2] + __ldcg(p));
                }
                __syncthreads();
            }
            if (tid == 0) red_rel_or(&g_pz[t], 1 << s);
        }

        // ===== epilogue: 16 cols per CTA =====
        if (tid == 0) while (ld_acq(&g_pz[t]) != 0xF) {}
        __syncthreads();
        {
            int n = 16 * s + (tid & 15);
            int r0 = (tid >> 4) * 4;
            float4 p0 = __ldcg((const float4*)&g_P[(t * 2 + 0) * 4096 + n * 64 + r0]);
            float4 p1 = __ldcg((const float4*)&g_P[(t * 2 + 1) * 4096 + n * 64 + r0]);
            float4 zi4 = __ldcg((const float4*)&zb[(192 + n) * 64 + r0]);
            float4 zl4 = __ldcg((const float4*)&zb[(256 + n) * 64 + r0]);
            float4 zt4 = __ldcg((const float4*)&zb[(320 + n) * 64 + r0]);
            float4 zd4 = __ldcg((const float4*)&zb[(384 + n) * 64 + r0]);
            float4 xw4 = __ldcg((const float4*)0 == 0 ? (const float4*)&g_xWij[0] : 0);
#pragma unroll
            for (int e = 0; e < 4; ++e) {
                int row = r0 + e;
                float zi = (&zi4.x)[e], zl = (&zl4.x)[e];
                float zt = (&zt4.x)[e], zd = (&zd4.x)[e];
                float m = fmaxf(fmaxf(zi, zl), fmaxf(zt, zd));
                float ei = __expf(zi - m), el = __expf(zl - m);
                float et = __expf(zt - m), ed = __expf(zd - m);
                float inv = 1.f / (ei + el + et + ed);
                float ht = __bfloat162float(Ah[row * LDA + n]) +
                           __bfloat162float(Al[row * LDA + n]);
                float hl = __bfloat162float(Ah[row * LDA + 64 + n]) +
                           __bfloat162float(Al[row * LDA + 64 + n]);
                float hd = __bfloat162float(Ah[row * LDA + 128 + n]) +
                           __bfloat162float(Al[row * LDA + 128 + n]);
                float pre = __ldcg(&g_xWij[t * 4096 + row * 64 + n]) +
                            (&p0.x)[e] + (&p1.x)[e];
                pre = fminf(fmaxf(pre, -15.f), 15.f);
                float e2 = __expf(2.f * pre);
                float hh = (e2 - 1.f) / (e2 + 1.f);
                float h = (el * hl + et * ht + ed * hd + ei * hh) * inv;
                __nv_bfloat16 hhi = __float2bfloat16(h);
                __nv_bfloat16 hlo = __float2bfloat16(h - __bfloat162float(hhi));
                uint32_t pk = (uint32_t)__bfloat16_as_ushort(hhi) |
                              ((uint32_t)__bfloat16_as_ushort(hlo) << 16);
                __stcg(&g_Spk[t * 4096 + row * 64 + n], pk);
                if (t == 1023) out[row * 64 + n] = h;
            }
        }
        __syncthreads();
        if (tid == 0) red_rel_or(&g_hdone[t], 1 << s);
    }
}

// ---------------------------------------------------------------------------
extern "C" void kernel_launch(void* const* d_in, const int* in_sizes, int n_in,
                              void* d_out, int out_size) {
    const float* in   = (const float*)d_in[0];  // (64,64,32,32)
    const float* W    = (const float*)d_in[1];  // (256,448)
    const float* Urec = (const float*)d_in[2];  // (192,64)
    const float* bias = (const float*)d_in[3];  // (512)
    const float* Wij  = (const float*)d_in[4];  // (64,64)
    float* out = (float*)d_out;                 // (64,64)

    static int done = 0;
    if (!done) {
        cudaFuncSetAttribute(k_scan, cudaFuncAttributeMaxDynamicSharedMemorySize,
                             SMEMSZ);
        done = 1;
    }
    k_init<<<4, 256>>>();
    k_transpose<<<dim3(32, 2, 64), dim3(32, 32)>>>(in);
    k_pre<<<dim3(1024, 8), TPB>>>(W, Wij, bias);
    k_scan<<<128, TPB, SMEMSZ>>>(W, Urec, out);
}

// round 15
// speedup vs baseline: 1.4129x; 1.4129x over previous
#include <cuda_runtime.h>
#include <cuda_bf16.h>
#include <cstdint>
#include <math.h>

// SpatialGRU 32x32, B=64,U=64,C=64.
// R15: 32 groups x 4 CTAs/cell. r-CTAs (s=0,1): 96 r-cols -> G -> split-K P.
// z-CTAs (s=2,3): 4-gate columns for n-range 32 each -> Z stays in smem ->
// local softmax epilogue. XZ/xW prefetched to smem off the critical path.

#define TPB 256
#define LDA 200
#define LDW 200
#define LDUK 104
#define LDZ 65

__device__ float    g_x[1024 * 4096];
__device__ float    g_XZ[1024 * 28672];   // x@W+bias, col-major [c448][r64] (read-only in scan)
__device__ float    g_xWij[1024 * 4096];  // [t][r][n] (read-only in scan)
__device__ uint32_t g_Spk[1024 * 4096];   // packed h: lo16 = hi-bf16, hi16 = lo-bf16
__device__ float    g_P[1024 * 2 * 4096]; // partials, [row][n]
__device__ int      g_pz[1024];           // bits 0,1 = P ready
__device__ int      g_hdone[1024];        // bits 0,1 = h halves; full = 3

// r-CTA smem offsets
#define RWH 51200
#define RWL 89600
#define RUH 128000
#define RUL 141312
#define RXZ 154624
#define RGH 179200
#define RGL 192512
#define RPS 205824
// z-CTA smem offsets
#define ZWH 51200
#define ZWL 102400
#define ZXZ 153600
#define ZXW 186368
#define ZZS 194560
#define SMEMSZ 227840

static __device__ __forceinline__ void mma16816(float* c, const uint32_t* a,
                                                const uint32_t* b) {
    asm volatile(
        "mma.sync.aligned.m16n8k16.row.col.f32.bf16.bf16.f32 "
        "{%0,%1,%2,%3}, {%4,%5,%6,%7}, {%8,%9}, {%0,%1,%2,%3};"
        : "+f"(c[0]), "+f"(c[1]), "+f"(c[2]), "+f"(c[3])
        : "r"(a[0]), "r"(a[1]), "r"(a[2]), "r"(a[3]), "r"(b[0]), "r"(b[1]));
}
static __device__ __forceinline__ int ld_acq(const int* p) {
    int v;
    asm volatile("ld.acquire.gpu.global.b32 %0, [%1];" : "=r"(v) : "l"(p) : "memory");
    return v;
}
static __device__ __forceinline__ void red_rel_or(int* p, int v) {
    asm volatile("red.release.gpu.global.or.b32 [%0], %1;" :: "l"(p), "r"(v) : "memory");
}
static __device__ __forceinline__ void bfsplit(float v, __nv_bfloat16* hi, __nv_bfloat16* lo) {
    __nv_bfloat16 h = __float2bfloat16(v);
    *hi = h;
    *lo = __float2bfloat16(v - __bfloat162float(h));
}

// ---------------------------------------------------------------------------
__global__ void k_init() {
    int idx = blockIdx.x * blockDim.x + threadIdx.x;
    if (idx < 1024) { g_pz[idx] = 0; g_hdone[idx] = 0; }
}

__global__ void k_transpose(const float* __restrict__ in) {
    __shared__ float tile[32][33];
    int b = blockIdx.z, t0 = blockIdx.x * 32, c0 = blockIdx.y * 32;
    int tx = threadIdx.x, ty = threadIdx.y;
    tile[ty][tx] = in[b * 65536 + (c0 + ty) * 1024 + t0 + tx];
    __syncthreads();
    g_x[(t0 + ty) * 4096 + b * 64 + c0 + tx] = tile[tx][ty];
}

// XZ[t] = x@W[192:256]+bias[:448] (col-major [c][r]); xWij[t] = x@W_ij + b_ij
__global__ void k_pre(const float* __restrict__ W, const float* __restrict__ Wij,
                      const float* __restrict__ bias) {
    __shared__ float sXT[64 * 65];
    __shared__ float sB[64 * 64];
    int t = blockIdx.x, ct = blockIdx.y, tid = threadIdx.x;
    for (int idx = tid; idx < 4096; idx += TPB) {
        int rr = idx >> 6, k = idx & 63;
        sXT[k * 65 + rr] = g_x[t * 4096 + idx];
        sB[idx] = (ct < 7) ? W[(192 + rr) * 448 + ct * 64 + k] : Wij[rr * 64 + k];
    }
    __syncthreads();
    int r = tid & 63, cb = (tid >> 6) << 4;
    const float* bs = (ct < 7) ? (bias + ct * 64 + cb) : (bias + 448 + cb);
    float acc[16];
#pragma unroll
    for (int s = 0; s < 16; ++s) acc[s] = bs[s];
#pragma unroll 4
    for (int k = 0; k < 64; ++k) {
        float a = sXT[k * 65 + r];
        const float4* bp = (const float4*)&sB[k * 64 + cb];
        float4 b0 = bp[0], b1 = bp[1], b2 = bp[2], b3 = bp[3];
        acc[0] += a*b0.x; acc[1] += a*b0.y; acc[2] += a*b0.z; acc[3] += a*b0.w;
        acc[4] += a*b1.x; acc[5] += a*b1.y; acc[6] += a*b1.z; acc[7] += a*b1.w;
        acc[8] += a*b2.x; acc[9] += a*b2.y; acc[10] += a*b2.z; acc[11] += a*b2.w;
        acc[12] += a*b3.x; acc[13] += a*b3.y; acc[14] += a*b3.z; acc[15] += a*b3.w;
    }
    __syncthreads();
    if (ct < 7) {
#pragma unroll
        for (int s = 0; s < 16; ++s) sB[(cb + s) * 64 + r] = acc[s];
        __syncthreads();
        for (int idx = tid; idx < 4096; idx += TPB) {
            int c = idx >> 6, r2 = idx & 63;
            g_XZ[t * 28672 + (ct * 64 + c) * 64 + r2] = sB[c * 64 + r2];
        }
    } else {
        float* o = &g_xWij[t * 4096 + r * 64 + cb];
#pragma unroll
        for (int s = 0; s < 16; ++s) o[s] = acc[s];
    }
}

// ---------------------------------------------------------------------------
__global__ void __launch_bounds__(TPB, 1)
k_scan(const float* __restrict__ W, const float* __restrict__ Urec,
       float* __restrict__ out) {
    extern __shared__ char sm[];
    __nv_bfloat16* Ah = (__nv_bfloat16*)(sm);
    __nv_bfloat16* Al = (__nv_bfloat16*)(sm + 25600);

    int tid = threadIdx.x, w = tid >> 5, lane = tid & 31;
    int g = lane >> 2, q = lane & 3;
    int gp = blockIdx.x >> 2, s = blockIdx.x & 3;
    bool isr = (s < 2);
    int zs = s - 2;
    int rb = (w & 3) * 16, cg = w >> 2;

    __nv_bfloat16* Wh = (__nv_bfloat16*)(sm + 51200);
    __nv_bfloat16* Wl = (__nv_bfloat16*)(sm + (isr ? RWL : ZWL));
    __nv_bfloat16* Uh = (__nv_bfloat16*)(sm + RUH);
    __nv_bfloat16* Ul = (__nv_bfloat16*)(sm + RUL);
    float* XZr = (float*)(sm + RXZ);
    __nv_bfloat16* Gh = (__nv_bfloat16*)(sm + RGH);
    __nv_bfloat16* Gl = (__nv_bfloat16*)(sm + RGL);
    float* PS  = (float*)(sm + RPS);
    float* XZz = (float*)(sm + ZXZ);
    float* xws = (float*)(sm + ZXW);
    float* Zs  = (float*)(sm + ZZS);

    // resident W slice
    int wcols = isr ? 96 : 128;
    for (int idx = tid; idx < wcols * 192; idx += TPB) {
        int cl = idx % wcols, k = idx / wcols;
        int gcol = isr ? (s * 96 + cl)
                       : (192 + (cl >> 5) * 64 + zs * 32 + (cl & 31));
        bfsplit(W[k * 448 + gcol], &Wh[cl * LDW + k], &Wl[cl * LDW + k]);
    }
    // resident U slice (r only): rows s*96..s*96+95 of Urec (already LTD order)
    if (isr)
        for (int idx = tid; idx < 64 * 96; idx += TPB) {
            int n = idx & 63, k = idx >> 6;
            bfsplit(Urec[(s * 96 + k) * 64 + n], &Uh[n * LDUK + k], &Ul[n * LDUK + k]);
        }
    __syncthreads();

    for (int d = 0; d < 63; ++d) {
        int i0 = d > 31 ? d - 31 : 0;
        int nc = (d < 32) ? d + 1 : 63 - d;
        if (gp >= nc) continue;
        int i = i0 + gp, j = d - i, t = i * 32 + j;
        const uint32_t* hpT = (i > 0) ? &g_Spk[(t - 32) * 4096] : (const uint32_t*)0;
        const uint32_t* hpL = (j > 0) ? &g_Spk[(t - 1) * 4096] : (const uint32_t*)0;
        const uint32_t* hpD = (i > 0 && j > 0) ? &g_Spk[(t - 33) * 4096] : (const uint32_t*)0;

        // ---- prefetch (independent of neighbors) ----
        if (isr) {
            for (int idx = tid; idx < 96 * 64; idx += TPB) {
                int cl = idx >> 6, row = idx & 63;
                XZr[idx] = __ldg(&g_XZ[t * 28672 + (s * 96 + cl) * 64 + row]);
            }
        } else {
            for (int idx = tid; idx < 128 * 64; idx += TPB) {
                int cl = idx >> 6, row = idx & 63;
                int gcol = 192 + (cl >> 5) * 64 + zs * 32 + (cl & 31);
                XZz[idx] = __ldg(&g_XZ[t * 28672 + gcol * 64 + row]);
            }
            for (int idx = tid; idx < 2048; idx += TPB) {
                int row = idx >> 5, nn = idx & 31;
                xws[idx] = __ldg(&g_xWij[t * 4096 + row * 64 + zs * 32 + nn]);
            }
        }

        // ---- dependency wait ----
        if (tid == 0 && hpT)  while (ld_acq(&g_hdone[t - 32]) != 3) {}
        if (tid == 32 && hpL) while (ld_acq(&g_hdone[t - 1])  != 3) {}
        if (tid == 64 && hpD) while (ld_acq(&g_hdone[t - 33]) != 3) {}
        __syncthreads();

        // ---- A build: [top|left|diag] from packed h ----
        const uint4* bp3[3] = {(const uint4*)hpT, (const uint4*)hpL, (const uint4*)hpD};
#pragma unroll
        for (int it = 0; it < 12; ++it) {
            int idx = tid + it * TPB;
            int blk = idx >> 10, row = (idx >> 4) & 63, c4 = idx & 15;
            const uint4* p = bp3[blk];
            uint4 v = p ? __ldcg(&p[row * 16 + c4]) : make_uint4(0, 0, 0, 0);
            int cc = blk * 64 + c4 * 4;
            uint32_t* ah = (uint32_t*)&Ah[row * LDA + cc];
            uint32_t* al = (uint32_t*)&Al[row * LDA + cc];
            ah[0] = (v.x & 0xFFFFu) | (v.y << 16);
            ah[1] = (v.z & 0xFFFFu) | (v.w << 16);
            al[0] = (v.x >> 16) | (v.y & 0xFFFF0000u);
            al[1] = (v.z >> 16) | (v.w & 0xFFFF0000u);
        }
        __syncthreads();

        if (isr) {
            // ===== r-CTA: Z(96) -> G -> P =====
            float C[6][4];
#pragma unroll
            for (int a = 0; a < 6; ++a)
#pragma unroll
                for (int b = 0; b < 4; ++b) C[a][b] = 0.f;
#pragma unroll 1
            for (int kc = 0; kc < 12; ++kc) {
                int kb = kc * 16;
                uint32_t ah[4], al[4];
                ah[0] = *(const uint32_t*)&Ah[(rb + g) * LDA + kb + q * 2];
                ah[1] = *(const uint32_t*)&Ah[(rb + g + 8) * LDA + kb + q * 2];
                ah[2] = *(const uint32_t*)&Ah[(rb + g) * LDA + kb + 8 + q * 2];
                ah[3] = *(const uint32_t*)&Ah[(rb + g + 8) * LDA + kb + 8 + q * 2];
                al[0] = *(const uint32_t*)&Al[(rb + g) * LDA + kb + q * 2];
                al[1] = *(const uint32_t*)&Al[(rb + g + 8) * LDA + kb + q * 2];
                al[2] = *(const uint32_t*)&Al[(rb + g) * LDA + kb + 8 + q * 2];
                al[3] = *(const uint32_t*)&Al[(rb + g + 8) * LDA + kb + 8 + q * 2];
#pragma unroll
                for (int nb = 0; nb < 6; ++nb) {
                    int n = cg * 48 + nb * 8 + g;
                    uint32_t bh[2], bl[2];
                    bh[0] = *(const uint32_t*)&Wh[n * LDW + kb + q * 2];
                    bh[1] = *(const uint32_t*)&Wh[n * LDW + kb + 8 + q * 2];
                    bl[0] = *(const uint32_t*)&Wl[n * LDW + kb + q * 2];
                    bl[1] = *(const uint32_t*)&Wl[n * LDW + kb + 8 + q * 2];
                    mma16816(C[nb], ah, bh);
                    mma16816(C[nb], al, bh);
                    mma16816(C[nb], ah, bl);
                }
            }
            // G (compact r-order): G[row][cl] = sigmoid(Z+XZ) * A[row][amap]
#pragma unroll
            for (int nb = 0; nb < 6; ++nb)
#pragma unroll
                for (int e = 0; e < 4; ++e) {
                    int row = rb + g + ((e & 2) ? 8 : 0);
                    int cl = cg * 48 + nb * 8 + q * 2 + (e & 1);
                    float z = C[nb][e] + XZr[cl * 64 + row];
                    float sg = 1.f / (1.f + __expf(-z));
                    int rc = s * 96 + cl;
                    int ac = rc < 64 ? 64 + rc : (rc < 128 ? rc - 64 : rc);
                    float a = __bfloat162float(Ah[row * LDA + ac]) +
                              __bfloat162float(Al[row * LDA + ac]);
                    bfsplit(sg * a, &Gh[row * LDUK + cl], &Gl[row * LDUK + cl]);
                }
            __syncthreads();

            // P = G @ U (64x64, K=96)
            float P[4][4];
#pragma unroll
            for (int a = 0; a < 4; ++a)
#pragma unroll
                for (int b = 0; b < 4; ++b) P[a][b] = 0.f;
#pragma unroll 1
            for (int kc = 0; kc < 6; ++kc) {
                int kb = kc * 16;
                uint32_t ah[4], al[4];
                ah[0] = *(const uint32_t*)&Gh[(rb + g) * LDUK + kb + q * 2];
                ah[1] = *(const uint32_t*)&Gh[(rb + g + 8) * LDUK + kb + q * 2];
                ah[2] = *(const uint32_t*)&Gh[(rb + g) * LDUK + kb + 8 + q * 2];
                ah[3] = *(const uint32_t*)&Gh[(rb + g + 8) * LDUK + kb + 8 + q * 2];
                al[0] = *(const uint32_t*)&Gl[(rb + g) * LDUK + kb + q * 2];
                al[1] = *(const uint32_t*)&Gl[(rb + g + 8) * LDUK + kb + q * 2];
                al[2] = *(const uint32_t*)&Gl[(rb + g) * LDUK + kb + 8 + q * 2];
                al[3] = *(const uint32_t*)&Gl[(rb + g + 8) * LDUK + kb + 8 + q * 2];
#pragma unroll
                for (int nb = 0; nb < 4; ++nb) {
                    int n = cg * 32 + nb * 8 + g;
                    uint32_t bh[2], bl[2];
                    bh[0] = *(const uint32_t*)&Uh[n * LDUK + kb + q * 2];
                    bh[1] = *(const uint32_t*)&Uh[n * LDUK + kb + 8 + q * 2];
                    bl[0] = *(const uint32_t*)&Ul[n * LDUK + kb + q * 2];
                    bl[1] = *(const uint32_t*)&Ul[n * LDUK + kb + 8 + q * 2];
                    mma16816(P[nb], ah, bh);
                    mma16816(P[nb], al, bh);
                    mma16816(P[nb], ah, bl);
                }
            }
#pragma unroll
            for (int nb = 0; nb < 4; ++nb)
#pragma unroll
                for (int e = 0; e < 4; ++e) {
                    int row = rb + g + ((e & 2) ? 8 : 0);
                    int n = cg * 32 + nb * 8 + q * 2 + (e & 1);
                    PS[row * LDZ + n] = P[nb][e];
                }
            __syncthreads();
#pragma unroll
            for (int it = 0; it < 16; ++it) {
                int idx = tid + it * TPB;
                int r2 = idx >> 6, n2 = idx & 63;
                __stcg(&g_P[(t * 2 + s) * 4096 + idx], PS[r2 * LDZ + n2]);
            }
            __syncthreads();
            if (tid == 0) red_rel_or(&g_pz[t], 1 << s);
        } else {
            // ===== z-CTA: Z (128 gate-cols for own n-range) stays local =====
            float C[8][4];
#pragma unroll
            for (int a = 0; a < 8; ++a)
#pragma unroll
                for (int b = 0; b < 4; ++b) C[a][b] = 0.f;
#pragma unroll 1
            for (int kc = 0; kc < 12; ++kc) {
                int kb = kc * 16;
                uint32_t ah[4], al[4];
                ah[0] = *(const uint32_t*)&Ah[(rb + g) * LDA + kb + q * 2];
                ah[1] = *(const uint32_t*)&Ah[(rb + g + 8) * LDA + kb + q * 2];
                ah[2] = *(const uint32_t*)&Ah[(rb + g) * LDA + kb + 8 + q * 2];
                ah[3] = *(const uint32_t*)&Ah[(rb + g + 8) * LDA + kb + 8 + q * 2];
                al[0] = *(const uint32_t*)&Al[(rb + g) * LDA + kb + q * 2];
                al[1] = *(const uint32_t*)&Al[(rb + g + 8) * LDA + kb + q * 2];
                al[2] = *(const uint32_t*)&Al[(rb + g) * LDA + kb + 8 + q * 2];
                al[3] = *(const uint32_t*)&Al[(rb + g + 8) * LDA + kb + 8 + q * 2];
#pragma unroll
                for (int nb = 0; nb < 8; ++nb) {
                    int n = cg * 64 + nb * 8 + g;
                    uint32_t bh[2], bl[2];
                    bh[0] = *(const uint32_t*)&Wh[n * LDW + kb + q * 2];
                    bh[1] = *(const uint32_t*)&Wh[n * LDW + kb + 8 + q * 2];
                    bl[0] = *(const uint32_t*)&Wl[n * LDW + kb + q * 2];
                    bl[1] = *(const uint32_t*)&Wl[n * LDW + kb + 8 + q * 2];
                    mma16816(C[nb], ah, bh);
                    mma16816(C[nb], al, bh);
                    mma16816(C[nb], ah, bl);
                }
            }
#pragma unroll
            for (int nb = 0; nb < 8; ++nb)
#pragma unroll
                for (int e = 0; e < 4; ++e) {
                    int row = rb + g + ((e & 2) ? 8 : 0);
                    int cl = cg * 64 + nb * 8 + q * 2 + (e & 1);
                    Zs[cl * LDZ + row] = C[nb][e];
                }
            if (tid == 0) while ((ld_acq(&g_pz[t]) & 3) != 3) {}
            __syncthreads();

            // ---- epilogue: 32 n-cols, fully local ----
            int np = tid & 31;
            int r0 = (tid >> 5) * 8;
            int n = zs * 32 + np;
#pragma unroll
            for (int e = 0; e < 8; ++e) {
                int row = r0 + e;
                float zi = Zs[np * LDZ + row]          + XZz[np * 64 + row];
                float zl = Zs[(32 + np) * LDZ + row]   + XZz[(32 + np) * 64 + row];
                float zt = Zs[(64 + np) * LDZ + row]   + XZz[(64 + np) * 64 + row];
                float zd = Zs[(96 + np) * LDZ + row]   + XZz[(96 + np) * 64 + row];
                float m = fmaxf(fmaxf(zi, zl), fmaxf(zt, zd));
                float ei = __expf(zi - m), el = __expf(zl - m);
                float et = __expf(zt - m), ed = __expf(zd - m);
                float inv = 1.f / (ei + el + et + ed);
                float ht = __bfloat162float(Ah[row * LDA + n]) +
                           __bfloat162float(Al[row * LDA + n]);
                float hl = __bfloat162float(Ah[row * LDA + 64 + n]) +
                           __bfloat162float(Al[row * LDA + 64 + n]);
                float hd = __bfloat162float(Ah[row * LDA + 128 + n]) +
                           __bfloat162float(Al[row * LDA + 128 + n]);
                float p0 = __ldcg(&g_P[(t * 2 + 0) * 4096 + row * 64 + n]);
                float p1 = __ldcg(&g_P[(t * 2 + 1) * 4096 + row * 64 + n]);
                float pre = xws[row * 32 + np] + p0 + p1;
                pre = fminf(fmaxf(pre, -15.f), 15.f);
                float e2 = __expf(2.f * pre);
                float hh = (e2 - 1.f) / (e2 + 1.f);
                float h = (el * hl + et * ht + ed * hd + ei * hh) * inv;
                __nv_bfloat16 hhi = __float2bfloat16(h);
                __nv_bfloat16 hlo = __float2bfloat16(h - __bfloat162float(hhi));
                uint32_t pk = (uint32_t)__bfloat16_as_ushort(hhi) |
                              ((uint32_t)__bfloat16_as_ushort(hlo) << 16);
                __stcg(&g_Spk[t * 4096 + row * 64 + n], pk);
                if (t == 1023) out[row * 64 + n] = h;
            }
            __syncthreads();
            if (tid == 0) red_rel_or(&g_hdone[t], 1 << zs);
        }
    }
}

// ---------------------------------------------------------------------------
extern "C" void kernel_launch(void* const* d_in, const int* in_sizes, int n_in,
                              void* d_out, int out_size) {
    const float* in   = (const float*)d_in[0];  // (64,64,32,32)
    const float* W    = (const float*)d_in[1];  // (256,448)
    const float* Urec = (const float*)d_in[2];  // (192,64)
    const float* bias = (const float*)d_in[3];  // (512)
    const float* Wij  = (const float*)d_in[4];  // (64,64)
    float* out = (float*)d_out;                 // (64,64)

    static int done = 0;
    if (!done) {
        cudaFuncSetAttribute(k_scan, cudaFuncAttributeMaxDynamicSharedMemorySize,
                             SMEMSZ);
        done = 1;
    }
    k_init<<<4, 256>>>();
    k_transpose<<<dim3(32, 2, 64), dim3(32, 32)>>>(in);
    k_pre<<<dim3(1024, 8), TPB>>>(W, Wij, bias);
    k_scan<<<128, TPB, SMEMSZ>>>(W, Urec, out);
}